// round 1
// baseline (speedup 1.0000x reference)
#include <cuda_runtime.h>
#include <cstdint>

// SliceTexture bilinear lookup, GB300 sm_103a.
// texture: [1024,1024,17] f32, uv: [N,2] f32 in [0,1]
// outputs (concatenated): values [N,16], homogeneous [N,1], vnn [N,17]

static constexpr int Wd = 1024;
static constexpr int Hd = 1024;
static constexpr int Cd = 17;

static constexpr int PTS     = 64;   // points per block
static constexpr int THREADS = 256;

// SMEM tex tile stride: 81 floats. 81 mod 32 == 17, which makes the
// 17-channel runs in phase C map to all-distinct banks across a warp.
static constexpr int TEX_STRIDE = 81;
static constexpr int VNN_STRIDE = 18;

__global__ __launch_bounds__(THREADS)
void slice_texture_kernel(const float* __restrict__ tex,
                          const float* __restrict__ uv,
                          float* __restrict__ out_values,   // [N,16]
                          float* __restrict__ out_h,        // [N,1]
                          float* __restrict__ out_vnn,      // [N,17]
                          int N)
{
    __shared__ int   s_base[PTS];                  // index of tex[y0, x0, 0]
    __shared__ float s_fx[PTS];
    __shared__ float s_fy[PTS];
    __shared__ float s_tex[PTS * TEX_STRIDE];      // per point: [0..33] top pair, [34..67] bottom pair
    __shared__ float s_vnn[PTS * VNN_STRIDE];

    const int tid = threadIdx.x;
    const int p0  = blockIdx.x * PTS;
    const int np  = min(PTS, N - p0);              // points handled by this block

    // ---- Phase A: per-point index + weight computation -------------------
    if (tid < np) {
        const float2 uvv = reinterpret_cast<const float2*>(uv)[p0 + tid];
        float x = uvv.x * (float)(Wd - 1);
        float y = uvv.y * (float)(Hd - 1);
        int x0 = (int)floorf(x);
        int y0 = (int)floorf(y);
        x0 = max(0, min(x0, Wd - 2));
        y0 = max(0, min(y0, Hd - 2));
        s_fx[tid]   = x - (float)x0;
        s_fy[tid]   = y - (float)y0;
        s_base[tid] = (y0 * Wd + x0) * Cd;
    }
    __syncthreads();

    // ---- Phase B: cooperative texel staging ------------------------------
    // 68 floats per point: [0..33]  = tex[y0,   x0..x0+1, :]  (34 contiguous floats)
    //                      [34..67] = tex[y0+1, x0..x0+1, :]
    if (np == PTS) {
        // Full tile: fully unrolled for MLP (17 independent LDGs in flight).
        #pragma unroll
        for (int it = 0; it < (PTS * 68) / THREADS; ++it) {
            const int idx = tid + it * THREADS;
            const int p   = idx / 68;
            const int e   = idx - p * 68;
            const int off = (e < 34) ? e : (e - 34) + Wd * Cd;
            s_tex[p * TEX_STRIDE + e] = __ldg(tex + s_base[p] + off);
        }
    } else {
        for (int idx = tid; idx < np * 68; idx += THREADS) {
            const int p   = idx / 68;
            const int e   = idx - p * 68;
            const int off = (e < 34) ? e : (e - 34) + Wd * Cd;
            s_tex[p * TEX_STRIDE + e] = __ldg(tex + s_base[p] + off);
        }
    }
    __syncthreads();

    // ---- Phase C: bilinear blend, coalesced vnn store --------------------
    for (int idx = tid; idx < np * Cd; idx += THREADS) {
        const int p = idx / Cd;
        const int c = idx - p * Cd;
        const float fx = s_fx[p];
        const float fy = s_fy[p];
        const float* tp = &s_tex[p * TEX_STRIDE];
        const float t00 = tp[c];
        const float t01 = tp[Cd + c];
        const float t10 = tp[34 + c];
        const float t11 = tp[34 + Cd + c];
        const float top = t00 * (1.0f - fx) + t01 * fx;
        const float bot = t10 * (1.0f - fx) + t11 * fx;
        const float v   = top * (1.0f - fy) + bot * fy;
        s_vnn[p * VNN_STRIDE + c] = v;
        out_vnn[(size_t)(p0 + p) * Cd + c] = v;
    }
    __syncthreads();

    // ---- Phase D: normalized values + homogeneous, coalesced -------------
    for (int idx = tid; idx < np * (Cd - 1); idx += THREADS) {
        const int p = idx >> 4;          // /16
        const int c = idx & 15;
        const float h = s_vnn[p * VNN_STRIDE + (Cd - 1)];
        const float v = s_vnn[p * VNN_STRIDE + c];
        out_values[(size_t)(p0 + p) * (Cd - 1) + c] = __fdividef(v, h + 1e-5f);
    }
    if (tid < np) {
        out_h[p0 + tid] = s_vnn[tid * VNN_STRIDE + (Cd - 1)];
    }
}

extern "C" void kernel_launch(void* const* d_in, const int* in_sizes, int n_in,
                              void* d_out, int out_size)
{
    const float* tex = (const float*)d_in[0];     // [1024,1024,17]
    const float* uv  = (const float*)d_in[1];     // [N,2]
    const int N = in_sizes[1] / 2;

    float* out        = (float*)d_out;
    float* out_values = out;                                 // N*16
    float* out_h      = out + (size_t)N * (Cd - 1);          // N*1
    float* out_vnn    = out + (size_t)N * Cd;                // N*17

    const int blocks = (N + PTS - 1) / PTS;
    slice_texture_kernel<<<blocks, THREADS>>>(tex, uv, out_values, out_h, out_vnn, N);
}

// round 2
// speedup vs baseline: 1.3484x; 1.3484x over previous
#include <cuda_runtime.h>
#include <cstdint>

// SliceTexture bilinear lookup, GB300 sm_103a — R2: float4 staging, register-carried v.
// texture: [1024,1024,17] f32, uv: [N,2] f32 in [0,1]
// outputs (concatenated): values [N,16], homogeneous [N,1], vnn [N,17]

static constexpr int Wd = 1024;
static constexpr int Hd = 1024;
static constexpr int Cd = 17;
static constexpr int ROWF = Wd * Cd;                 // 17408 floats per texture row (div by 4)
static constexpr int ROW4 = ROWF / 4;                // 4352 float4 per row
static constexpr int TEXF = Hd * Wd * Cd;            // 17,825,792 floats (div by 4)
static constexpr int TEX4 = TEXF / 4;                // 4,456,448 float4

static constexpr int PTS     = 64;                   // points per block
static constexpr int THREADS = 256;

// Per-point staging: 10 float4 (top span) + 10 float4 (bottom span), stride 21 for banks.
static constexpr int ST4 = 21;                       // float4 stride per point
static constexpr int STF = ST4 * 4;                  // 84 floats

__global__ __launch_bounds__(THREADS)
void slice_texture_kernel(const float4* __restrict__ tex4,
                          const float*  __restrict__ uv,
                          float* __restrict__ out_values,   // [N,16]
                          float* __restrict__ out_h,        // [N,1]
                          float* __restrict__ out_vnn,      // [N,17]
                          int N)
{
    __shared__ float4 s_tex4[PTS * ST4];     // 21504 B
    __shared__ int    s_a4[PTS];             // aligned float4 index of top span
    __shared__ int    s_sh[PTS];             // shift = base & 3 (same for both spans)
    __shared__ float  s_fx[PTS];
    __shared__ float  s_fy[PTS];
    __shared__ float  s_h[PTS];              // homogeneous channel per point

    const int tid = threadIdx.x;
    const int p0  = blockIdx.x * PTS;
    const int np  = min(PTS, N - p0);

    // ---- Phase A: per-point setup ----------------------------------------
    if (tid < np) {
        const float2 uvv = reinterpret_cast<const float2*>(uv)[p0 + tid];
        float x = uvv.x * (float)(Wd - 1);
        float y = uvv.y * (float)(Hd - 1);
        int x0 = (int)floorf(x);
        int y0 = (int)floorf(y);
        x0 = max(0, min(x0, Wd - 2));
        y0 = max(0, min(y0, Hd - 2));
        const int base = (y0 * Wd + x0) * Cd;
        s_fx[tid] = x - (float)x0;
        s_fy[tid] = y - (float)y0;
        s_a4[tid] = base >> 2;               // aligned-down float4 index
        s_sh[tid] = base & 3;
    }
    __syncthreads();

    // ---- Phase B: float4 texel staging ------------------------------------
    // Work item w = p*20 + j: j in [0,10) -> top-span float4 j, j in [10,20) -> bottom float4 j-10.
    // 64 pts * 20 = 1280 items = 5 * 256 threads. Consecutive lanes -> consecutive addresses.
    #pragma unroll
    for (int k = 0; k < (PTS * 20) / THREADS; ++k) {
        const int w = tid + k * THREADS;
        const int p = w / 20;                // mul-shift
        const int j = w - p * 20;
        if (p < np) {
            const bool bot = (j >= 10);
            int idx4 = s_a4[p] + (bot ? (ROW4 + j - 10) : j);
            idx4 = min(idx4, TEX4 - 1);      // needed float4s are always in-bounds; clamp over-read
            s_tex4[p * ST4 + j] = __ldg(tex4 + idx4);
        }
    }
    __syncthreads();

    // ---- Phase C: bilinear blend, v stays in registers --------------------
    // Work item idx = p*17 + c, 1088 items = 4*256 + 64.
    constexpr int ITERS = (PTS * Cd + THREADS - 1) / THREADS;   // 5
    float vreg[ITERS];
    const int lim = np * Cd;

    #pragma unroll
    for (int i = 0; i < ITERS; ++i) {
        const int idx = tid + i * THREADS;
        if (idx < lim) {
            const int p = idx / 17;          // mul-shift
            const int c = idx - p * 17;
            const float fx = s_fx[p];
            const float fy = s_fy[p];
            const int   sh = s_sh[p];
            const float* st = reinterpret_cast<const float*>(&s_tex4[p * ST4]);
            const float t00 = st[sh + c];
            const float t01 = st[sh + c + Cd];
            const float t10 = st[40 + sh + c];
            const float t11 = st[40 + sh + c + Cd];
            const float top = t00 + (t01 - t00) * fx;
            const float bot = t10 + (t11 - t10) * fx;
            const float v   = top + (bot - top) * fy;
            vreg[i] = v;
            out_vnn[(size_t)(p0 + p) * Cd + c] = v;
            if (c == Cd - 1) s_h[p] = v;
        }
    }
    __syncthreads();

    // ---- Phase D: normalized values + homogeneous -------------------------
    #pragma unroll
    for (int i = 0; i < ITERS; ++i) {
        const int idx = tid + i * THREADS;
        if (idx < lim) {
            const int p = idx / 17;
            const int c = idx - p * 17;
            const float v = vreg[i];
            if (c < Cd - 1) {
                const float h = s_h[p];
                out_values[(size_t)(p0 + p) * (Cd - 1) + c] = __fdividef(v, h + 1e-5f);
            } else {
                out_h[p0 + p] = v;
            }
        }
    }
}

extern "C" void kernel_launch(void* const* d_in, const int* in_sizes, int n_in,
                              void* d_out, int out_size)
{
    const float4* tex4 = (const float4*)d_in[0];   // [1024,1024,17] f32 (16B-aligned base)
    const float*  uv   = (const float*)d_in[1];    // [N,2]
    const int N = in_sizes[1] / 2;

    float* out        = (float*)d_out;
    float* out_values = out;                               // N*16
    float* out_h      = out + (size_t)N * (Cd - 1);        // N*1
    float* out_vnn    = out + (size_t)N * Cd;              // N*17

    const int blocks = (N + PTS - 1) / PTS;
    slice_texture_kernel<<<blocks, THREADS>>>(tex4, uv, out_values, out_h, out_vnn, N);
}

// round 3
// speedup vs baseline: 1.4449x; 1.0715x over previous
#include <cuda_runtime.h>
#include <cstdint>

// SliceTexture bilinear lookup, GB300 sm_103a — R3.
// 4-lanes-per-point blend, packed meta LDS.128, fused normalize, streaming stores.
// texture: [1024,1024,17] f32, uv: [N,2] f32 in [0,1]
// outputs (concatenated): values [N,16], homogeneous [N,1], vnn [N,17]

static constexpr int Wd = 1024;
static constexpr int Hd = 1024;
static constexpr int Cd = 17;
static constexpr int ROWF = Wd * Cd;        // 17408 floats per texture row
static constexpr int ROW4 = ROWF / 4;       // 4352 float4 per row
static constexpr int TEX4 = (Hd * Wd * Cd) / 4;   // 4,456,448 float4

static constexpr int PTS     = 64;          // points per block
static constexpr int THREADS = 256;
static constexpr int ST4     = 21;          // float4 stride/point (top: slots 0..9, bottom: 10..19)

__global__ __launch_bounds__(THREADS)
void slice_texture_kernel(const float4* __restrict__ tex4,
                          const float*  __restrict__ uv,
                          float* __restrict__ out_values,   // [N,16]
                          float* __restrict__ out_h,        // [N,1]
                          float* __restrict__ out_vnn,      // [N,17]
                          int N)
{
    __shared__ float4 s_tex[PTS * ST4];     // 21504 B
    __shared__ int    s_a4[PTS];            // aligned float4 index of top span
    __shared__ float4 s_meta[PTS];          // {fx, fy, bitcast(sh), -}

    const int tid = threadIdx.x;
    const int p0  = blockIdx.x * PTS;
    const int np  = min(PTS, N - p0);

    // ---- Phase A: per-point setup -----------------------------------------
    if (tid < np) {
        const float2 uvv = reinterpret_cast<const float2*>(uv)[p0 + tid];
        float x = uvv.x * (float)(Wd - 1);
        float y = uvv.y * (float)(Hd - 1);
        int x0 = (int)floorf(x);
        int y0 = (int)floorf(y);
        x0 = max(0, min(x0, Wd - 2));
        y0 = max(0, min(y0, Hd - 2));
        const int base = (y0 * Wd + x0) * Cd;
        s_a4[tid]   = base >> 2;
        s_meta[tid] = make_float4(x - (float)x0, y - (float)y0,
                                  __int_as_float(base & 3), 0.0f);
    }
    __syncthreads();

    // ---- Phase B: float4 texel staging (chunk-consecutive = best coalescing)
    // item w = p*20 + j: j<10 -> top-span chunk j, else bottom chunk j-10.
    #pragma unroll
    for (int k = 0; k < (PTS * 20) / THREADS; ++k) {
        const int w = tid + k * THREADS;
        const int p = w / 20;
        const int j = w - p * 20;
        if (p < np) {
            int idx4 = s_a4[p] + ((j < 10) ? j : (ROW4 - 10) + j);
            idx4 = min(idx4, TEX4 - 1);      // single OOB corner chunk -> harmless garbage
            s_tex[p * ST4 + j] = __ldg(tex4 + idx4);
        }
    }
    __syncthreads();

    // ---- Phase C: blend + normalize, 4 lanes per point ---------------------
    const int p = tid >> 2;                  // 0..63
    const int q = tid & 3;                   // 0..3 -> channels 4q..4q+3
    if (p < np) {
        const float4 m  = s_meta[p];
        const float  fx = m.x;
        const float  fy = m.y;
        const int    sh = __float_as_int(m.z);
        const float* st = reinterpret_cast<const float*>(&s_tex[p * ST4]) + sh;
        // bottom span starts at float 40 within the point's 84-float tile.

        // homogeneous channel (c = 16), computed by every lane (broadcast LDS)
        float h;
        {
            const float t00 = st[16],      t01 = st[33];
            const float t10 = st[40 + 16], t11 = st[40 + 33];
            const float top = t00 + (t01 - t00) * fx;
            const float bot = t10 + (t11 - t10) * fx;
            h = top + (bot - top) * fy;
        }

        float v[4];
        const int cb = q * 4;
        #pragma unroll
        for (int i = 0; i < 4; ++i) {
            const int c = cb + i;
            const float t00 = st[c],          t01 = st[c + Cd];
            const float t10 = st[40 + c],     t11 = st[40 + c + Cd];
            const float top = t00 + (t01 - t00) * fx;
            const float bot = t10 + (t11 - t10) * fx;
            v[i] = top + (bot - top) * fy;
        }

        const size_t pt = (size_t)(p0 + p);

        // vnn: scalar streaming stores (17-stride rows can't vectorize)
        float* vp = out_vnn + pt * Cd + cb;
        __stcs(vp + 0, v[0]);
        __stcs(vp + 1, v[1]);
        __stcs(vp + 2, v[2]);
        __stcs(vp + 3, v[3]);
        if (q == 0) {
            __stcs(out_vnn + pt * Cd + 16, h);
            __stcs(out_h + pt, h);
        }

        // values: one STG.128 per lane (16B aligned: (pt*16 + 4q) % 4 == 0)
        const float r = __fdividef(1.0f, h + 1e-5f);
        float4 vals;
        vals.x = v[0] * r;  vals.y = v[1] * r;
        vals.z = v[2] * r;  vals.w = v[3] * r;
        __stcs(reinterpret_cast<float4*>(out_values) + (pt * 4 + q), vals);
    }
}

extern "C" void kernel_launch(void* const* d_in, const int* in_sizes, int n_in,
                              void* d_out, int out_size)
{
    const float4* tex4 = (const float4*)d_in[0];   // [1024,1024,17] f32
    const float*  uv   = (const float*)d_in[1];    // [N,2]
    const int N = in_sizes[1] / 2;

    float* out        = (float*)d_out;
    float* out_values = out;                               // N*16
    float* out_h      = out + (size_t)N * (Cd - 1);        // N*1
    float* out_vnn    = out + (size_t)N * Cd;              // N*17

    const int blocks = (N + PTS - 1) / PTS;
    slice_texture_kernel<<<blocks, THREADS>>>(tex4, uv, out_values, out_h, out_vnn, N);
}

// round 6
// speedup vs baseline: 1.5361x; 1.0631x over previous
#include <cuda_runtime.h>
#include <cuda.h>
#include <cstdint>

// SliceTexture bilinear lookup, GB300 sm_103a — R6.
// Per-point TMA box {40,2} gather, 16B-aligned global coords (aligned-down + shift),
// 128B-aligned SMEM slots, __grid_constant__ tensormap (no device-side tmap writes).

static constexpr int Wd = 1024;
static constexpr int Hd = 1024;
static constexpr int Cd = 17;

static constexpr int PTS     = 64;
static constexpr int THREADS = 256;
static constexpr int TILE_F  = 128;              // floats per slot (512B = 4*128B)
static constexpr int BOX_W   = 40;               // box cols (160B rows, 16B multiple)
static constexpr int BOX_BYTES = BOX_W * 2 * 4;  // 320

__device__ __forceinline__ uint32_t smem_u32(const void* p) {
    uint32_t a;
    asm("{ .reg .u64 t; cvta.to.shared.u64 t, %1; cvt.u32.u64 %0, t; }" : "=r"(a) : "l"(p));
    return a;
}

__device__ __forceinline__ void mbar_wait_p0(uint32_t mbar) {
    asm volatile(
        "{\n\t.reg .pred P;\n\t"
        "W_%=: mbarrier.try_wait.parity.acquire.cta.shared::cta.b64 P, [%0], 0, 0x989680;\n\t"
        "@!P bra W_%=;\n\t}"
        :: "r"(mbar) : "memory");
}

// ---------------------------------------------------------------------------
// TMA kernel
// ---------------------------------------------------------------------------
__global__ __launch_bounds__(THREADS)
void slice_tma_kernel(const __grid_constant__ CUtensorMap tmap,
                      const float* __restrict__ uv,
                      float* __restrict__ out_values,   // [N,16]
                      float* __restrict__ out_h,        // [N,1]
                      float* __restrict__ out_vnn,      // [N,17]
                      int N)
{
    __shared__ alignas(128) float s_tile[PTS * TILE_F];   // 32768 B
    __shared__ float4 s_meta[PTS];                        // {fx, fy, bitcast(sh), 0}
    __shared__ alignas(8) unsigned long long s_mbar;

    const int tid = threadIdx.x;
    const int p0  = blockIdx.x * PTS;
    const int np  = min(PTS, N - p0);
    const uint32_t mbar = smem_u32(&s_mbar);

    if (tid == 0) {
        asm volatile("mbarrier.init.shared.b64 [%0], %1;" :: "r"(mbar), "r"(PTS) : "memory");
    }
    __syncthreads();

    // ---- Phase A: setup + per-point TMA issue (threads 0..63) -------------
    if (tid < PTS) {
        if (tid < np) {
            const float2 uvv = reinterpret_cast<const float2*>(uv)[p0 + tid];
            float x = uvv.x * (float)(Wd - 1);
            float y = uvv.y * (float)(Hd - 1);
            int x0 = (int)floorf(x);
            int y0 = (int)floorf(y);
            x0 = max(0, min(x0, Wd - 2));
            y0 = max(0, min(y0, Hd - 2));
            const int base = x0 * Cd;                 // column (element) index in row y0
            const int c0   = base & ~3;               // 16B-aligned start column
            s_meta[tid] = make_float4(x - (float)x0, y - (float)y0,
                                      __int_as_float(base & 3), 0.0f);

            const uint32_t dst = smem_u32(s_tile) + tid * (TILE_F * 4);  // 512B slots
            asm volatile("mbarrier.arrive.expect_tx.shared.b64 _, [%0], %1;"
                         :: "r"(mbar), "r"(BOX_BYTES) : "memory");
            asm volatile(
                "cp.async.bulk.tensor.2d.shared::cta.global.tile.mbarrier::complete_tx::bytes "
                "[%0], [%1, {%2, %3}], [%4];"
                :: "r"(dst), "l"(&tmap), "r"(c0), "r"(y0), "r"(mbar)
                : "memory");
        } else {
            asm volatile("mbarrier.arrive.shared.b64 _, [%0];" :: "r"(mbar) : "memory");
        }
    }

    // arrive(release) above pairs with this acquire: s_meta + s_tile visible.
    mbar_wait_p0(mbar);

    // ---- Phase C: one point per warp, lanes 0..16 = channels ---------------
    // Slot layout: row y0 = floats [0..39], row y0+1 = floats [40..79].
    // Actual texel c of (y0,x0) at sh + c; of (y0,x0+1) at sh + 17 + c.
    const int warp = tid >> 5;
    const int lane = tid & 31;
    #pragma unroll
    for (int it = 0; it < PTS / 8; ++it) {
        const int p = it * 8 + warp;
        if (p < np && lane < Cd) {
            const float4 m  = s_meta[p];
            const int    sh = __float_as_int(m.z);
            const float* st = &s_tile[p * TILE_F] + sh + lane;
            const float t00 = st[0],  t01 = st[17];
            const float t10 = st[40], t11 = st[57];
            const float top = t00 + (t01 - t00) * m.x;
            const float bot = t10 + (t11 - t10) * m.x;
            const float v   = top + (bot - top) * m.y;
            const float h   = __shfl_sync(0x1ffffu, v, 16);

            const size_t pt = (size_t)(p0 + p);
            __stcs(out_vnn + pt * Cd + lane, v);
            if (lane < Cd - 1) {
                __stcs(out_values + pt * (Cd - 1) + lane,
                       v * __fdividef(1.0f, h + 1e-5f));
            } else {
                __stcs(out_h + pt, v);
            }
        }
    }
}

// ---------------------------------------------------------------------------
// Fallback (R3 LDG kernel, 166us known-good) — used only if encode fails
// ---------------------------------------------------------------------------
static constexpr int ROW4 = (Wd * Cd) / 4;
static constexpr int TEX4 = (Hd * Wd * Cd) / 4;
static constexpr int ST4  = 21;

__global__ __launch_bounds__(THREADS)
void slice_ldg_kernel(const float4* __restrict__ tex4,
                      const float*  __restrict__ uv,
                      float* __restrict__ out_values,
                      float* __restrict__ out_h,
                      float* __restrict__ out_vnn,
                      int N)
{
    __shared__ float4 s_tex[PTS * ST4];
    __shared__ int    s_a4[PTS];
    __shared__ float4 s_meta[PTS];

    const int tid = threadIdx.x;
    const int p0  = blockIdx.x * PTS;
    const int np  = min(PTS, N - p0);

    if (tid < np) {
        const float2 uvv = reinterpret_cast<const float2*>(uv)[p0 + tid];
        float x = uvv.x * (float)(Wd - 1);
        float y = uvv.y * (float)(Hd - 1);
        int x0 = (int)floorf(x);
        int y0 = (int)floorf(y);
        x0 = max(0, min(x0, Wd - 2));
        y0 = max(0, min(y0, Hd - 2));
        const int base = (y0 * Wd + x0) * Cd;
        s_a4[tid]   = base >> 2;
        s_meta[tid] = make_float4(x - (float)x0, y - (float)y0,
                                  __int_as_float(base & 3), 0.0f);
    }
    __syncthreads();

    #pragma unroll
    for (int k = 0; k < (PTS * 20) / THREADS; ++k) {
        const int w = tid + k * THREADS;
        const int p = w / 20;
        const int j = w - p * 20;
        if (p < np) {
            int idx4 = s_a4[p] + ((j < 10) ? j : (ROW4 - 10) + j);
            idx4 = min(idx4, TEX4 - 1);
            s_tex[p * ST4 + j] = __ldg(tex4 + idx4);
        }
    }
    __syncthreads();

    const int p = tid >> 2;
    const int q = tid & 3;
    if (p < np) {
        const float4 m  = s_meta[p];
        const float  fx = m.x, fy = m.y;
        const int    sh = __float_as_int(m.z);
        const float* st = reinterpret_cast<const float*>(&s_tex[p * ST4]) + sh;
        float h;
        {
            const float t00 = st[16], t01 = st[33];
            const float t10 = st[56], t11 = st[73];
            const float top = t00 + (t01 - t00) * fx;
            const float bot = t10 + (t11 - t10) * fx;
            h = top + (bot - top) * fy;
        }
        float v[4];
        const int cb = q * 4;
        #pragma unroll
        for (int i = 0; i < 4; ++i) {
            const int c = cb + i;
            const float t00 = st[c],      t01 = st[c + Cd];
            const float t10 = st[40 + c], t11 = st[40 + c + Cd];
            const float top = t00 + (t01 - t00) * fx;
            const float bot = t10 + (t11 - t10) * fx;
            v[i] = top + (bot - top) * fy;
        }
        const size_t pt = (size_t)(p0 + p);
        float* vp = out_vnn + pt * Cd + cb;
        __stcs(vp + 0, v[0]); __stcs(vp + 1, v[1]);
        __stcs(vp + 2, v[2]); __stcs(vp + 3, v[3]);
        if (q == 0) { __stcs(out_vnn + pt * Cd + 16, h); __stcs(out_h + pt, h); }
        const float r = __fdividef(1.0f, h + 1e-5f);
        float4 vals = make_float4(v[0]*r, v[1]*r, v[2]*r, v[3]*r);
        __stcs(reinterpret_cast<float4*>(out_values) + (pt * 4 + q), vals);
    }
}

// ---------------------------------------------------------------------------
// Host
// ---------------------------------------------------------------------------
typedef CUresult (*PFN_TMapEncode)(CUtensorMap*, CUtensorMapDataType, cuuint32_t,
                                   void*, const cuuint64_t*, const cuuint64_t*,
                                   const cuuint32_t*, const cuuint32_t*,
                                   CUtensorMapInterleave, CUtensorMapSwizzle,
                                   CUtensorMapL2promotion, CUtensorMapFloatOOBfill);

extern "C" void kernel_launch(void* const* d_in, const int* in_sizes, int n_in,
                              void* d_out, int out_size)
{
    const float* tex = (const float*)d_in[0];     // [1024,1024,17]
    const float* uv  = (const float*)d_in[1];     // [N,2]
    const int N = in_sizes[1] / 2;

    float* out        = (float*)d_out;
    float* out_values = out;
    float* out_h      = out + (size_t)N * (Cd - 1);
    float* out_vnn    = out + (size_t)N * Cd;

    const int blocks = (N + PTS - 1) / PTS;

    void* fn = nullptr;
    cudaDriverEntryPointQueryResult qr = cudaDriverEntryPointSymbolNotFound;
    cudaError_t e = cudaGetDriverEntryPointByVersion(
        "cuTensorMapEncodeTiled", &fn, 12000, cudaEnableDefault, &qr);
    bool tma_ok = (e == cudaSuccess) && (qr == cudaDriverEntryPointSuccess) && fn;

    CUtensorMap tmap;
    if (tma_ok) {
        cuuint64_t dims[2]    = { (cuuint64_t)(Wd * Cd), (cuuint64_t)Hd };   // [17408, 1024]
        cuuint64_t strides[1] = { (cuuint64_t)(Wd * Cd) * sizeof(float) };  // 69632
        cuuint32_t box[2]     = { BOX_W, 2 };
        cuuint32_t es[2]      = { 1, 1 };
        CUresult r = ((PFN_TMapEncode)fn)(
            &tmap, CU_TENSOR_MAP_DATA_TYPE_FLOAT32, 2, (void*)tex,
            dims, strides, box, es,
            CU_TENSOR_MAP_INTERLEAVE_NONE, CU_TENSOR_MAP_SWIZZLE_NONE,
            CU_TENSOR_MAP_L2_PROMOTION_L2_128B, CU_TENSOR_MAP_FLOAT_OOB_FILL_NONE);
        tma_ok = (r == CUDA_SUCCESS);
    }

    if (tma_ok) {
        slice_tma_kernel<<<blocks, THREADS>>>(tmap, uv, out_values, out_h, out_vnn, N);
    } else {
        slice_ldg_kernel<<<blocks, THREADS>>>((const float4*)tex, uv,
                                              out_values, out_h, out_vnn, N);
    }
}

// round 7
// speedup vs baseline: 1.9074x; 1.2417x over previous
#include <cuda_runtime.h>
#include <cuda.h>
#include <cstdint>

// SliceTexture bilinear lookup, GB300 sm_103a — R7.
// Per-point TMA box {40,2} gather (16B-aligned coords, 384B SMEM slots),
// consume: 2 points per warp (half-warp = 16 channels), leader computes h and
// 1/(h+eps), shfl-broadcast reciprocal, fully coalesced stores.

static constexpr int Wd = 1024;
static constexpr int Hd = 1024;
static constexpr int Cd = 17;

static constexpr int PTS     = 64;
static constexpr int THREADS = 256;
static constexpr int TILE_F  = 96;               // floats per slot (384B = 3*128B)
static constexpr int BOX_W   = 40;               // box cols (160B rows)
static constexpr int BOX_BYTES = BOX_W * 2 * 4;  // 320

__device__ __forceinline__ uint32_t smem_u32(const void* p) {
    uint32_t a;
    asm("{ .reg .u64 t; cvta.to.shared.u64 t, %1; cvt.u32.u64 %0, t; }" : "=r"(a) : "l"(p));
    return a;
}

__device__ __forceinline__ void mbar_wait_p0(uint32_t mbar) {
    asm volatile(
        "{\n\t.reg .pred P;\n\t"
        "W_%=: mbarrier.try_wait.parity.acquire.cta.shared::cta.b64 P, [%0], 0, 0x989680;\n\t"
        "@!P bra W_%=;\n\t}"
        :: "r"(mbar) : "memory");
}

// ---------------------------------------------------------------------------
// TMA kernel
// ---------------------------------------------------------------------------
__global__ __launch_bounds__(THREADS)
void slice_tma_kernel(const __grid_constant__ CUtensorMap tmap,
                      const float* __restrict__ uv,
                      float* __restrict__ out_values,   // [N,16]
                      float* __restrict__ out_h,        // [N,1]
                      float* __restrict__ out_vnn,      // [N,17]
                      int N)
{
    __shared__ alignas(128) float s_tile[PTS * TILE_F];   // 24576 B
    __shared__ float4 s_meta[PTS];                        // {fx, fy, bitcast(sh), 0}
    __shared__ alignas(8) unsigned long long s_mbar;

    const int tid = threadIdx.x;
    const int p0  = blockIdx.x * PTS;
    const int np  = min(PTS, N - p0);
    const uint32_t mbar = smem_u32(&s_mbar);

    if (tid == 0) {
        asm volatile("mbarrier.init.shared.b64 [%0], %1;" :: "r"(mbar), "r"(PTS) : "memory");
    }
    __syncthreads();

    // ---- Phase A: setup + per-point TMA issue (threads 0..63) -------------
    if (tid < PTS) {
        if (tid < np) {
            const float2 uvv = reinterpret_cast<const float2*>(uv)[p0 + tid];
            float x = uvv.x * (float)(Wd - 1);
            float y = uvv.y * (float)(Hd - 1);
            int x0 = (int)floorf(x);
            int y0 = (int)floorf(y);
            x0 = max(0, min(x0, Wd - 2));
            y0 = max(0, min(y0, Hd - 2));
            const int base = x0 * Cd;                 // element column in row y0
            const int c0   = base & ~3;               // 16B-aligned start column
            s_meta[tid] = make_float4(x - (float)x0, y - (float)y0,
                                      __int_as_float(base & 3), 0.0f);

            const uint32_t dst = smem_u32(s_tile) + tid * (TILE_F * 4);  // 384B slots
            asm volatile("mbarrier.arrive.expect_tx.shared.b64 _, [%0], %1;"
                         :: "r"(mbar), "r"(BOX_BYTES) : "memory");
            asm volatile(
                "cp.async.bulk.tensor.2d.shared::cta.global.tile.mbarrier::complete_tx::bytes "
                "[%0], [%1, {%2, %3}], [%4];"
                :: "r"(dst), "l"(&tmap), "r"(c0), "r"(y0), "r"(mbar)
                : "memory");
        } else {
            asm volatile("mbarrier.arrive.shared.b64 _, [%0];" :: "r"(mbar) : "memory");
        }
    }

    // arrive(release) above pairs with this acquire: s_meta + s_tile visible.
    mbar_wait_p0(mbar);

    // ---- Phase C: 2 points per warp (half-warp = 16 channels) -------------
    // Slot layout: texel c of (y0,x0) at sh+c; (y0,x0+1) at sh+17+c;
    //              (y0+1,x0) at 40+sh+c; (y0+1,x0+1) at 57+sh+c.
    const int warp = tid >> 5;
    const int lane = tid & 31;
    const int half = lane >> 4;          // 0 = point A, 1 = point B
    const int c    = lane & 15;          // channel 0..15
    #pragma unroll
    for (int it = 0; it < PTS / 16; ++it) {           // 4 iterations
        const int p   = (it * 8 + warp) * 2 + half;
        const bool act = (p < np);
        const int pc  = act ? p : (np - 1);           // clamp: keep warp converged

        const float4 m  = s_meta[pc];
        const int    sh = __float_as_int(m.z);
        const float* st = &s_tile[pc * TILE_F] + sh;

        const float t00 = st[c],      t01 = st[c + 17];
        const float t10 = st[40 + c], t11 = st[57 + c];
        const float top = t00 + (t01 - t00) * m.x;
        const float bot = t10 + (t11 - t10) * m.x;
        const float v   = top + (bot - top) * m.y;

        float hv = 0.0f, rv = 0.0f;
        if (c == 0) {                                 // leader: channel 16 + reciprocal
            const float s00 = st[16], s01 = st[33];
            const float s10 = st[56], s11 = st[73];
            const float stp = s00 + (s01 - s00) * m.x;
            const float sbt = s10 + (s11 - s10) * m.x;
            hv = stp + (sbt - stp) * m.y;
            rv = __fdividef(1.0f, hv + 1e-5f);
        }
        const float r = __shfl_sync(0xffffffffu, rv, lane & 16);

        if (act) {
            const size_t pt = (size_t)(p0 + p);
            __stcs(out_vnn + pt * Cd + c, v);
            __stcs(out_values + pt * (Cd - 1) + c, v * r);
            if (c == 0) {
                __stcs(out_vnn + pt * Cd + 16, hv);
                __stcs(out_h + pt, hv);
            }
        }
    }
}

// ---------------------------------------------------------------------------
// Fallback (R3 LDG kernel, 166us known-good) — used only if encode fails
// ---------------------------------------------------------------------------
static constexpr int ROW4 = (Wd * Cd) / 4;
static constexpr int TEX4 = (Hd * Wd * Cd) / 4;
static constexpr int ST4  = 21;

__global__ __launch_bounds__(THREADS)
void slice_ldg_kernel(const float4* __restrict__ tex4,
                      const float*  __restrict__ uv,
                      float* __restrict__ out_values,
                      float* __restrict__ out_h,
                      float* __restrict__ out_vnn,
                      int N)
{
    __shared__ float4 s_tex[PTS * ST4];
    __shared__ int    s_a4[PTS];
    __shared__ float4 s_meta[PTS];

    const int tid = threadIdx.x;
    const int p0  = blockIdx.x * PTS;
    const int np  = min(PTS, N - p0);

    if (tid < np) {
        const float2 uvv = reinterpret_cast<const float2*>(uv)[p0 + tid];
        float x = uvv.x * (float)(Wd - 1);
        float y = uvv.y * (float)(Hd - 1);
        int x0 = (int)floorf(x);
        int y0 = (int)floorf(y);
        x0 = max(0, min(x0, Wd - 2));
        y0 = max(0, min(y0, Hd - 2));
        const int base = (y0 * Wd + x0) * Cd;
        s_a4[tid]   = base >> 2;
        s_meta[tid] = make_float4(x - (float)x0, y - (float)y0,
                                  __int_as_float(base & 3), 0.0f);
    }
    __syncthreads();

    #pragma unroll
    for (int k = 0; k < (PTS * 20) / THREADS; ++k) {
        const int w = tid + k * THREADS;
        const int p = w / 20;
        const int j = w - p * 20;
        if (p < np) {
            int idx4 = s_a4[p] + ((j < 10) ? j : (ROW4 - 10) + j);
            idx4 = min(idx4, TEX4 - 1);
            s_tex[p * ST4 + j] = __ldg(tex4 + idx4);
        }
    }
    __syncthreads();

    const int p = tid >> 2;
    const int q = tid & 3;
    if (p < np) {
        const float4 m  = s_meta[p];
        const float  fx = m.x, fy = m.y;
        const int    sh = __float_as_int(m.z);
        const float* st = reinterpret_cast<const float*>(&s_tex[p * ST4]) + sh;
        float h;
        {
            const float t00 = st[16], t01 = st[33];
            const float t10 = st[56], t11 = st[73];
            const float top = t00 + (t01 - t00) * fx;
            const float bot = t10 + (t11 - t10) * fx;
            h = top + (bot - top) * fy;
        }
        float v[4];
        const int cb = q * 4;
        #pragma unroll
        for (int i = 0; i < 4; ++i) {
            const int ch = cb + i;
            const float t00 = st[ch],      t01 = st[ch + Cd];
            const float t10 = st[40 + ch], t11 = st[40 + ch + Cd];
            const float top = t00 + (t01 - t00) * fx;
            const float bot = t10 + (t11 - t10) * fx;
            v[i] = top + (bot - top) * fy;
        }
        const size_t pt = (size_t)(p0 + p);
        float* vp = out_vnn + pt * Cd + cb;
        __stcs(vp + 0, v[0]); __stcs(vp + 1, v[1]);
        __stcs(vp + 2, v[2]); __stcs(vp + 3, v[3]);
        if (q == 0) { __stcs(out_vnn + pt * Cd + 16, h); __stcs(out_h + pt, h); }
        const float r = __fdividef(1.0f, h + 1e-5f);
        float4 vals = make_float4(v[0]*r, v[1]*r, v[2]*r, v[3]*r);
        __stcs(reinterpret_cast<float4*>(out_values) + (pt * 4 + q), vals);
    }
}

// ---------------------------------------------------------------------------
// Host
// ---------------------------------------------------------------------------
typedef CUresult (*PFN_TMapEncode)(CUtensorMap*, CUtensorMapDataType, cuuint32_t,
                                   void*, const cuuint64_t*, const cuuint64_t*,
                                   const cuuint32_t*, const cuuint32_t*,
                                   CUtensorMapInterleave, CUtensorMapSwizzle,
                                   CUtensorMapL2promotion, CUtensorMapFloatOOBfill);

extern "C" void kernel_launch(void* const* d_in, const int* in_sizes, int n_in,
                              void* d_out, int out_size)
{
    const float* tex = (const float*)d_in[0];     // [1024,1024,17]
    const float* uv  = (const float*)d_in[1];     // [N,2]
    const int N = in_sizes[1] / 2;

    float* out        = (float*)d_out;
    float* out_values = out;
    float* out_h      = out + (size_t)N * (Cd - 1);
    float* out_vnn    = out + (size_t)N * Cd;

    const int blocks = (N + PTS - 1) / PTS;

    void* fn = nullptr;
    cudaDriverEntryPointQueryResult qr = cudaDriverEntryPointSymbolNotFound;
    cudaError_t e = cudaGetDriverEntryPointByVersion(
        "cuTensorMapEncodeTiled", &fn, 12000, cudaEnableDefault, &qr);
    bool tma_ok = (e == cudaSuccess) && (qr == cudaDriverEntryPointSuccess) && fn;

    CUtensorMap tmap;
    if (tma_ok) {
        cuuint64_t dims[2]    = { (cuuint64_t)(Wd * Cd), (cuuint64_t)Hd };   // [17408, 1024]
        cuuint64_t strides[1] = { (cuuint64_t)(Wd * Cd) * sizeof(float) };  // 69632
        cuuint32_t box[2]     = { BOX_W, 2 };
        cuuint32_t es[2]      = { 1, 1 };
        CUresult r = ((PFN_TMapEncode)fn)(
            &tmap, CU_TENSOR_MAP_DATA_TYPE_FLOAT32, 2, (void*)tex,
            dims, strides, box, es,
            CU_TENSOR_MAP_INTERLEAVE_NONE, CU_TENSOR_MAP_SWIZZLE_NONE,
            CU_TENSOR_MAP_L2_PROMOTION_L2_128B, CU_TENSOR_MAP_FLOAT_OOB_FILL_NONE);
        tma_ok = (r == CUDA_SUCCESS);
    }

    if (tma_ok) {
        slice_tma_kernel<<<blocks, THREADS>>>(tmap, uv, out_values, out_h, out_vnn, N);
    } else {
        slice_ldg_kernel<<<blocks, THREADS>>>((const float4*)tex, uv,
                                              out_values, out_h, out_vnn, N);
    }
}

// round 8
// speedup vs baseline: 2.1289x; 1.1162x over previous
#include <cuda_runtime.h>
#include <cuda.h>
#include <cstdint>

// SliceTexture bilinear lookup, GB300 sm_103a — R8.
// Per-point TMA box {40,2} gather; dense h-phase (threads 0..63) computes
// homogeneous channel + reciprocal into s_r; main loop 2 pts/warp with no
// leader branch / no shfl; fully coalesced stores.

static constexpr int Wd = 1024;
static constexpr int Hd = 1024;
static constexpr int Cd = 17;

static constexpr int PTS     = 64;
static constexpr int THREADS = 256;
static constexpr int TILE_F  = 96;               // floats per slot (384B = 3*128B)
static constexpr int BOX_W   = 40;               // box cols (160B rows)
static constexpr int BOX_BYTES = BOX_W * 2 * 4;  // 320

__device__ __forceinline__ uint32_t smem_u32(const void* p) {
    uint32_t a;
    asm("{ .reg .u64 t; cvta.to.shared.u64 t, %1; cvt.u32.u64 %0, t; }" : "=r"(a) : "l"(p));
    return a;
}

__device__ __forceinline__ void mbar_wait_p0(uint32_t mbar) {
    asm volatile(
        "{\n\t.reg .pred P;\n\t"
        "W_%=: mbarrier.try_wait.parity.acquire.cta.shared::cta.b64 P, [%0], 0, 0x989680;\n\t"
        "@!P bra W_%=;\n\t}"
        :: "r"(mbar) : "memory");
}

// ---------------------------------------------------------------------------
// TMA kernel
// ---------------------------------------------------------------------------
__global__ __launch_bounds__(THREADS)
void slice_tma_kernel(const __grid_constant__ CUtensorMap tmap,
                      const float* __restrict__ uv,
                      float* __restrict__ out_values,   // [N,16]
                      float* __restrict__ out_h,        // [N,1]
                      float* __restrict__ out_vnn,      // [N,17]
                      int N)
{
    __shared__ alignas(128) float s_tile[PTS * TILE_F];   // 24576 B
    __shared__ float4 s_meta[PTS];                        // {fx, fy, bitcast(sh), 0}
    __shared__ float  s_r[PTS];                           // 1/(h + 1e-5)
    __shared__ alignas(8) unsigned long long s_mbar;

    const int tid = threadIdx.x;
    const int p0  = blockIdx.x * PTS;
    const int np  = min(PTS, N - p0);
    const uint32_t mbar = smem_u32(&s_mbar);

    if (tid == 0) {
        asm volatile("mbarrier.init.shared.b64 [%0], %1;" :: "r"(mbar), "r"(PTS) : "memory");
    }
    __syncthreads();

    // ---- Phase A: setup + per-point TMA issue (threads 0..63) -------------
    if (tid < PTS) {
        if (tid < np) {
            const float2 uvv = reinterpret_cast<const float2*>(uv)[p0 + tid];
            float x = uvv.x * (float)(Wd - 1);
            float y = uvv.y * (float)(Hd - 1);
            int x0 = (int)floorf(x);
            int y0 = (int)floorf(y);
            x0 = max(0, min(x0, Wd - 2));
            y0 = max(0, min(y0, Hd - 2));
            const int base = x0 * Cd;                 // element column in row y0
            const int c0   = base & ~3;               // 16B-aligned start column
            s_meta[tid] = make_float4(x - (float)x0, y - (float)y0,
                                      __int_as_float(base & 3), 0.0f);

            const uint32_t dst = smem_u32(s_tile) + tid * (TILE_F * 4);  // 384B slots
            asm volatile("mbarrier.arrive.expect_tx.shared.b64 _, [%0], %1;"
                         :: "r"(mbar), "r"(BOX_BYTES) : "memory");
            asm volatile(
                "cp.async.bulk.tensor.2d.shared::cta.global.tile.mbarrier::complete_tx::bytes "
                "[%0], [%1, {%2, %3}], [%4];"
                :: "r"(dst), "l"(&tmap), "r"(c0), "r"(y0), "r"(mbar)
                : "memory");
        } else {
            asm volatile("mbarrier.arrive.shared.b64 _, [%0];" :: "r"(mbar) : "memory");
        }
    }

    // arrive(release) above pairs with this acquire: s_meta + s_tile visible.
    mbar_wait_p0(mbar);

    // ---- Phase H: homogeneous channel for all points, dense lanes ---------
    // Slot layout: texel c of (y0,x0) at sh+c; (y0,x0+1) at sh+17+c;
    //              (y0+1,x0) at 40+sh+c; (y0+1,x0+1) at 57+sh+c.
    if (tid < np) {
        const float4 m  = s_meta[tid];
        const int    sh = __float_as_int(m.z);
        const float* st = &s_tile[tid * TILE_F] + sh;
        const float s00 = st[16], s01 = st[33];
        const float s10 = st[56], s11 = st[73];
        const float stp = s00 + (s01 - s00) * m.x;
        const float sbt = s10 + (s11 - s10) * m.x;
        const float h   = stp + (sbt - stp) * m.y;
        s_r[tid] = __fdividef(1.0f, h + 1e-5f);
        const size_t pt = (size_t)(p0 + tid);
        __stcs(out_h + pt, h);
        __stcs(out_vnn + pt * Cd + 16, h);
    }
    __syncthreads();                                  // publish s_r

    // ---- Phase C: 2 points per warp (half-warp = 16 channels), branch-free -
    const int warp = tid >> 5;
    const int lane = tid & 31;
    const int half = lane >> 4;          // 0 = point A, 1 = point B
    const int c    = lane & 15;          // channel 0..15
    #pragma unroll
    for (int it = 0; it < PTS / 16; ++it) {           // 4 iterations
        const int p = (it * 8 + warp) * 2 + half;
        if (p < np) {
            const float4 m  = s_meta[p];
            const int    sh = __float_as_int(m.z);
            const float* st = &s_tile[p * TILE_F] + sh;

            const float t00 = st[c],      t01 = st[c + 17];
            const float t10 = st[40 + c], t11 = st[57 + c];
            const float top = t00 + (t01 - t00) * m.x;
            const float bot = t10 + (t11 - t10) * m.x;
            const float v   = top + (bot - top) * m.y;

            const size_t pt = (size_t)(p0 + p);
            __stcs(out_vnn + pt * Cd + c, v);
            __stcs(out_values + pt * (Cd - 1) + c, v * s_r[p]);
        }
    }
}

// ---------------------------------------------------------------------------
// Fallback (R3 LDG kernel, 166us known-good) — used only if encode fails
// ---------------------------------------------------------------------------
static constexpr int ROW4 = (Wd * Cd) / 4;
static constexpr int TEX4 = (Hd * Wd * Cd) / 4;
static constexpr int ST4  = 21;

__global__ __launch_bounds__(THREADS)
void slice_ldg_kernel(const float4* __restrict__ tex4,
                      const float*  __restrict__ uv,
                      float* __restrict__ out_values,
                      float* __restrict__ out_h,
                      float* __restrict__ out_vnn,
                      int N)
{
    __shared__ float4 s_tex[PTS * ST4];
    __shared__ int    s_a4[PTS];
    __shared__ float4 s_meta[PTS];

    const int tid = threadIdx.x;
    const int p0  = blockIdx.x * PTS;
    const int np  = min(PTS, N - p0);

    if (tid < np) {
        const float2 uvv = reinterpret_cast<const float2*>(uv)[p0 + tid];
        float x = uvv.x * (float)(Wd - 1);
        float y = uvv.y * (float)(Hd - 1);
        int x0 = (int)floorf(x);
        int y0 = (int)floorf(y);
        x0 = max(0, min(x0, Wd - 2));
        y0 = max(0, min(y0, Hd - 2));
        const int base = (y0 * Wd + x0) * Cd;
        s_a4[tid]   = base >> 2;
        s_meta[tid] = make_float4(x - (float)x0, y - (float)y0,
                                  __int_as_float(base & 3), 0.0f);
    }
    __syncthreads();

    #pragma unroll
    for (int k = 0; k < (PTS * 20) / THREADS; ++k) {
        const int w = tid + k * THREADS;
        const int p = w / 20;
        const int j = w - p * 20;
        if (p < np) {
            int idx4 = s_a4[p] + ((j < 10) ? j : (ROW4 - 10) + j);
            idx4 = min(idx4, TEX4 - 1);
            s_tex[p * ST4 + j] = __ldg(tex4 + idx4);
        }
    }
    __syncthreads();

    const int p = tid >> 2;
    const int q = tid & 3;
    if (p < np) {
        const float4 m  = s_meta[p];
        const float  fx = m.x, fy = m.y;
        const int    sh = __float_as_int(m.z);
        const float* st = reinterpret_cast<const float*>(&s_tex[p * ST4]) + sh;
        float h;
        {
            const float t00 = st[16], t01 = st[33];
            const float t10 = st[56], t11 = st[73];
            const float top = t00 + (t01 - t00) * fx;
            const float bot = t10 + (t11 - t10) * fx;
            h = top + (bot - top) * fy;
        }
        float v[4];
        const int cb = q * 4;
        #pragma unroll
        for (int i = 0; i < 4; ++i) {
            const int ch = cb + i;
            const float t00 = st[ch],      t01 = st[ch + Cd];
            const float t10 = st[40 + ch], t11 = st[40 + ch + Cd];
            const float top = t00 + (t01 - t00) * fx;
            const float bot = t10 + (t11 - t10) * fx;
            v[i] = top + (bot - top) * fy;
        }
        const size_t pt = (size_t)(p0 + p);
        float* vp = out_vnn + pt * Cd + cb;
        __stcs(vp + 0, v[0]); __stcs(vp + 1, v[1]);
        __stcs(vp + 2, v[2]); __stcs(vp + 3, v[3]);
        if (q == 0) { __stcs(out_vnn + pt * Cd + 16, h); __stcs(out_h + pt, h); }
        const float r = __fdividef(1.0f, h + 1e-5f);
        float4 vals = make_float4(v[0]*r, v[1]*r, v[2]*r, v[3]*r);
        __stcs(reinterpret_cast<float4*>(out_values) + (pt * 4 + q), vals);
    }
}

// ---------------------------------------------------------------------------
// Host
// ---------------------------------------------------------------------------
typedef CUresult (*PFN_TMapEncode)(CUtensorMap*, CUtensorMapDataType, cuuint32_t,
                                   void*, const cuuint64_t*, const cuuint64_t*,
                                   const cuuint32_t*, const cuuint32_t*,
                                   CUtensorMapInterleave, CUtensorMapSwizzle,
                                   CUtensorMapL2promotion, CUtensorMapFloatOOBfill);

extern "C" void kernel_launch(void* const* d_in, const int* in_sizes, int n_in,
                              void* d_out, int out_size)
{
    const float* tex = (const float*)d_in[0];     // [1024,1024,17]
    const float* uv  = (const float*)d_in[1];     // [N,2]
    const int N = in_sizes[1] / 2;

    float* out        = (float*)d_out;
    float* out_values = out;
    float* out_h      = out + (size_t)N * (Cd - 1);
    float* out_vnn    = out + (size_t)N * Cd;

    const int blocks = (N + PTS - 1) / PTS;

    void* fn = nullptr;
    cudaDriverEntryPointQueryResult qr = cudaDriverEntryPointSymbolNotFound;
    cudaError_t e = cudaGetDriverEntryPointByVersion(
        "cuTensorMapEncodeTiled", &fn, 12000, cudaEnableDefault, &qr);
    bool tma_ok = (e == cudaSuccess) && (qr == cudaDriverEntryPointSuccess) && fn;

    CUtensorMap tmap;
    if (tma_ok) {
        cuuint64_t dims[2]    = { (cuuint64_t)(Wd * Cd), (cuuint64_t)Hd };   // [17408, 1024]
        cuuint64_t strides[1] = { (cuuint64_t)(Wd * Cd) * sizeof(float) };  // 69632
        cuuint32_t box[2]     = { BOX_W, 2 };
        cuuint32_t es[2]      = { 1, 1 };
        CUresult r = ((PFN_TMapEncode)fn)(
            &tmap, CU_TENSOR_MAP_DATA_TYPE_FLOAT32, 2, (void*)tex,
            dims, strides, box, es,
            CU_TENSOR_MAP_INTERLEAVE_NONE, CU_TENSOR_MAP_SWIZZLE_NONE,
            CU_TENSOR_MAP_L2_PROMOTION_L2_128B, CU_TENSOR_MAP_FLOAT_OOB_FILL_NONE);
        tma_ok = (r == CUDA_SUCCESS);
    }

    if (tma_ok) {
        slice_tma_kernel<<<blocks, THREADS>>>(tmap, uv, out_values, out_h, out_vnn, N);
    } else {
        slice_ldg_kernel<<<blocks, THREADS>>>((const float4*)tex, uv,
                                              out_values, out_h, out_vnn, N);
    }
}